// round 1
// baseline (speedup 1.0000x reference)
#include <cuda_runtime.h>
#include <cuda_bf16.h>
#include <math.h>

// Shapes (fixed by the problem)
#define B_   8
#define LQ_  2048
#define LK_  2048
#define D_   256
#define H_   128

// Scratch (device globals: allocation-free per harness rules)
__device__ float g_pq[(size_t)B_ * LQ_ * H_];                 // relu(Q Wq^T)          [B,Lq,H]
__device__ float g_pk[(size_t)B_ * LK_ * H_];                 // relu(K Wk^T)*scaling  [B,Lk,H]
__device__ float g_S [(size_t)B_ * LQ_ * LK_];                // scores                [B,Lq,Lk]
__device__ float g_m1[B_ * LQ_], g_l1[B_ * LQ_];              // branch1 row stats (over k)
__device__ float g_m2[B_ * LK_], g_l2[B_ * LK_];              // branch2 col stats (over q)
__device__ unsigned char g_mask1[B_ * LK_];
__device__ unsigned char g_mask2[B_ * LQ_];
__device__ int g_mask_is_byte;

// ---------------------------------------------------------------------------
// Mask dtype canonicalization. If the masks arrived as int32 (0/1 LE), every
// byte at index i with (i&3)!=0 within the first N bytes is zero. A genuine
// 1-byte bool mask has random nonzero bytes everywhere.
// ---------------------------------------------------------------------------
__global__ void detect_mask_kernel(const unsigned char* m) {
    __shared__ int flag;
    if (threadIdx.x == 0) flag = 0;
    __syncthreads();
    for (int i = threadIdx.x; i < B_ * LK_; i += blockDim.x)
        if ((i & 3) && m[i]) flag = 1;
    __syncthreads();
    if (threadIdx.x == 0) g_mask_is_byte = flag;
}

__global__ void build_mask_kernel(const void* m1, const void* m2) {
    int i = blockIdx.x * blockDim.x + threadIdx.x;
    if (i >= B_ * LK_) return;
    if (g_mask_is_byte) {
        g_mask1[i] = ((const unsigned char*)m1)[i] ? 1 : 0;
        g_mask2[i] = ((const unsigned char*)m2)[i] ? 1 : 0;
    } else {
        g_mask1[i] = ((const int*)m1)[i] ? 1 : 0;
        g_mask2[i] = ((const int*)m2)[i] ? 1 : 0;
    }
}

// ---------------------------------------------------------------------------
// Projections: out[r,h] = relu(sum_d X[r,d] * W[h,d])  (* scaling[h] for pk)
// Block: 64 rows x 128 cols, 256 threads, thread tile 8x4, K-chunk 32.
// ---------------------------------------------------------------------------
__global__ void __launch_bounds__(256) proj_kernel(
    const float* __restrict__ Q, const float* __restrict__ K,
    const float* __restrict__ Wq, const float* __restrict__ Wk,
    const float* __restrict__ scaling)
{
    __shared__ float Xs[64][33];
    __shared__ float Ws[128][33];

    const int which = blockIdx.y;                 // 0: pq, 1: pk
    const float* X = which ? K : Q;
    const float* W = which ? Wk : Wq;
    float* out = which ? g_pk : g_pq;

    const int row0 = blockIdx.x * 64;
    const int tid = threadIdx.x;
    const int tr = tid >> 5;                      // 0..7  (same across a warp)
    const int tc = tid & 31;                      // 0..31

    float acc[8][4];
    #pragma unroll
    for (int i = 0; i < 8; i++)
        #pragma unroll
        for (int j = 0; j < 4; j++) acc[i][j] = 0.f;

    for (int k0 = 0; k0 < D_; k0 += 32) {
        #pragma unroll
        for (int t = 0; t < 8; t++) {             // Xs: 64x32
            int idx = tid + t * 256;
            int r = idx >> 5, kk = idx & 31;
            Xs[r][kk] = X[(size_t)(row0 + r) * D_ + k0 + kk];
        }
        #pragma unroll
        for (int t = 0; t < 16; t++) {            // Ws: 128x32
            int idx = tid + t * 256;
            int c = idx >> 5, kk = idx & 31;
            Ws[c][kk] = W[(size_t)c * D_ + k0 + kk];
        }
        __syncthreads();
        #pragma unroll
        for (int kk = 0; kk < 32; kk++) {
            float x[8], w[4];
            #pragma unroll
            for (int i = 0; i < 8; i++) x[i] = Xs[tr * 8 + i][kk];
            #pragma unroll
            for (int j = 0; j < 4; j++) w[j] = Ws[tc + 32 * j][kk];
            #pragma unroll
            for (int i = 0; i < 8; i++)
                #pragma unroll
                for (int j = 0; j < 4; j++)
                    acc[i][j] = fmaf(x[i], w[j], acc[i][j]);
        }
        __syncthreads();
    }

    #pragma unroll
    for (int i = 0; i < 8; i++) {
        int r = row0 + tr * 8 + i;
        #pragma unroll
        for (int j = 0; j < 4; j++) {
            int c = tc + 32 * j;
            float v = fmaxf(acc[i][j], 0.f);
            if (which) v *= scaling[c];
            out[(size_t)r * H_ + c] = v;
        }
    }
}

// ---------------------------------------------------------------------------
// scores[b] = pq[b] @ pk[b]^T : [2048,128] x [128,2048]
// Block: 64x64 tile, 256 threads, thread tile 4x4, K-chunk 64.
// ---------------------------------------------------------------------------
__global__ void __launch_bounds__(256) scores_kernel()
{
    __shared__ float As[64][69];
    __shared__ float Bs[64][69];

    const int b = blockIdx.z;
    const int row0 = blockIdx.y * 64;
    const int col0 = blockIdx.x * 64;
    const float* A  = g_pq + (size_t)b * LQ_ * H_;
    const float* Bm = g_pk + (size_t)b * LK_ * H_;
    float* S = g_S + (size_t)b * LQ_ * LK_;

    const int tid = threadIdx.x;
    const int tr = tid >> 4, tc = tid & 15;

    float acc[4][4];
    #pragma unroll
    for (int i = 0; i < 4; i++)
        #pragma unroll
        for (int j = 0; j < 4; j++) acc[i][j] = 0.f;

    for (int k0 = 0; k0 < H_; k0 += 64) {
        #pragma unroll
        for (int t = 0; t < 16; t++) {
            int idx = tid + t * 256;              // 0..4095
            int r = idx >> 6, kk = idx & 63;
            As[r][kk] = A [(size_t)(row0 + r) * H_ + k0 + kk];
            Bs[r][kk] = Bm[(size_t)(col0 + r) * H_ + k0 + kk];
        }
        __syncthreads();
        #pragma unroll
        for (int kk = 0; kk < 64; kk++) {
            float a[4], bb[4];
            #pragma unroll
            for (int i = 0; i < 4; i++) a[i]  = As[tr + 16 * i][kk];
            #pragma unroll
            for (int j = 0; j < 4; j++) bb[j] = Bs[tc + 16 * j][kk];
            #pragma unroll
            for (int i = 0; i < 4; i++)
                #pragma unroll
                for (int j = 0; j < 4; j++)
                    acc[i][j] = fmaf(a[i], bb[j], acc[i][j]);
        }
        __syncthreads();
    }

    #pragma unroll
    for (int i = 0; i < 4; i++)
        #pragma unroll
        for (int j = 0; j < 4; j++)
            S[(size_t)(row0 + tr + 16 * i) * LK_ + col0 + tc + 16 * j] = acc[i][j];
}

// ---------------------------------------------------------------------------
// Branch-1 stats: per (b,q): max & sum-exp over k, masked by g_mask1[b,k].
// One block per row, coalesced row read.
// ---------------------------------------------------------------------------
__global__ void __launch_bounds__(256) stats1_kernel()
{
    const int row = blockIdx.x;                   // b*2048 + q
    const int b = row >> 11;
    const float* Srow = g_S + (size_t)row * LK_;
    const unsigned char* mk = g_mask1 + (b << 11);
    const int tid = threadIdx.x;

    float vals[8];
    float m = -INFINITY;
    #pragma unroll
    for (int i = 0; i < 8; i++) {
        int k = tid + (i << 8);
        float s = Srow[k];
        vals[i] = mk[k] ? -INFINITY : s;
        m = fmaxf(m, vals[i]);
    }

    __shared__ float red[256];
    red[tid] = m;
    __syncthreads();
    for (int off = 128; off > 0; off >>= 1) {
        if (tid < off) red[tid] = fmaxf(red[tid], red[tid + off]);
        __syncthreads();
    }
    m = red[0];
    __syncthreads();

    float l = 0.f;
    #pragma unroll
    for (int i = 0; i < 8; i++) l += __expf(vals[i] - m);
    red[tid] = l;
    __syncthreads();
    for (int off = 128; off > 0; off >>= 1) {
        if (tid < off) red[tid] += red[tid + off];
        __syncthreads();
    }
    if (tid == 0) { g_m1[row] = m; g_l1[row] = red[0]; }
}

// ---------------------------------------------------------------------------
// Branch-2 stats: per (b,k): online max & sum-exp over q, masked by g_mask2[b,q].
// Block handles 64 columns; 4 q-strided partials per column; coalesced reads.
// ---------------------------------------------------------------------------
__global__ void __launch_bounds__(256) stats2_kernel()
{
    const int b = blockIdx.y;
    const int k0 = blockIdx.x * 64;
    const int tid = threadIdx.x;
    const int kk = tid & 63, qg = tid >> 6;
    const float* Sb = g_S + (size_t)b * LQ_ * LK_;
    const unsigned char* mk = g_mask2 + (b << 11);

    float m = -INFINITY, l = 0.f;
    for (int q = qg; q < LQ_; q += 4) {
        if (mk[q]) continue;
        float s = Sb[(size_t)q * LK_ + k0 + kk];
        if (s <= m) {
            l += __expf(s - m);
        } else {
            l = l * __expf(m - s) + 1.f;
            m = s;
        }
    }

    __shared__ float sm[256], sl[256];
    sm[tid] = m; sl[tid] = l;
    __syncthreads();
    if (tid < 64) {
        #pragma unroll
        for (int g = 1; g < 4; g++) {
            float m2 = sm[tid + 64 * g], l2 = sl[tid + 64 * g];
            if (m2 > m)          { l = l * __expf(m - m2) + l2; m = m2; }
            else if (l2 > 0.f)   { l += l2 * __expf(m2 - m); }
        }
        g_m2[(b << 11) + k0 + tid] = m;
        g_l2[(b << 11) + k0 + tid] = l;
    }
}

// ---------------------------------------------------------------------------
// Fused softmax-weighted GEMM for both branches.
//   br=0: out1[b,q,d] = sum_k exp(S[b,q,k]-m1)/l1 * (!mask1[b,k]) * V1[b,k,d]
//   br=1: out2[b,k,d] = sum_q exp(S[b,q,k]-m2)/l2 * (!mask2[b,q]) * V2[b,q,d]
// Block: 64 output rows x 256 d, 256 threads (4 q-groups x 64 d-threads),
// thread tile 16(rows) x 4(d). Inner-dim chunk 32.
// ---------------------------------------------------------------------------
__global__ void __launch_bounds__(256) branch_kernel(
    const float* __restrict__ V1, const float* __restrict__ V2,
    float* __restrict__ out)
{
    __shared__ __align__(16) float ws[64][33];
    __shared__ __align__(16) float vs[32][256];
    __shared__ float s_m[64], s_il[64];

    const int br2 = blockIdx.z;
    const int b = blockIdx.y;
    const int row0 = blockIdx.x * 64;

    const float* V = (br2 ? V2 : V1) + (size_t)b * 2048 * D_;
    const unsigned char* mk = (br2 ? g_mask2 : g_mask1) + (b << 11);
    const float* Sb = g_S + (size_t)b * LQ_ * LK_;
    const float* gm = (br2 ? g_m2 : g_m1) + (b << 11) + row0;
    const float* gl = (br2 ? g_l2 : g_l1) + (b << 11) + row0;
    float* o = out + (br2 ? (size_t)B_ * LQ_ * D_ : 0)
                   + ((size_t)(b << 11) + row0) * D_;

    const int tid = threadIdx.x;
    if (tid < 64) {
        s_m[tid]  = gm[tid];
        s_il[tid] = 1.f / gl[tid];
    }
    __syncthreads();

    const int dj = tid & 63, qg = tid >> 6;

    float acc[16][4];
    #pragma unroll
    for (int i = 0; i < 16; i++)
        #pragma unroll
        for (int j = 0; j < 4; j++) acc[i][j] = 0.f;

    for (int i0 = 0; i0 < 2048; i0 += 32) {
        // weight tile ws[row][inner] = exp(s - m) * invl, 0 if masked
        #pragma unroll
        for (int t = 0; t < 8; t++) {
            int idx = tid + t * 256;              // 0..2047
            int r, ii;
            float s;
            if (!br2) { r = idx >> 5; ii = idx & 31;
                        s = Sb[(size_t)(row0 + r) * LK_ + i0 + ii]; }
            else      { ii = idx >> 6; r = idx & 63;
                        s = Sb[(size_t)(i0 + ii) * LK_ + row0 + r]; }
            float w = 0.f;
            if (!mk[i0 + ii]) w = __expf(s - s_m[r]) * s_il[r];
            ws[r][ii] = w;
        }
        // V tile vs[32][256] via float4
        {
            const float4* src = reinterpret_cast<const float4*>(V + (size_t)i0 * D_);
            float4* dst = reinterpret_cast<float4*>(&vs[0][0]);
            #pragma unroll
            for (int t = 0; t < 8; t++) dst[tid + t * 256] = src[tid + t * 256];
        }
        __syncthreads();

        #pragma unroll
        for (int kk = 0; kk < 32; kk++) {
            float v0 = vs[kk][dj];
            float v1 = vs[kk][dj + 64];
            float v2 = vs[kk][dj + 128];
            float v3 = vs[kk][dj + 192];
            #pragma unroll
            for (int i = 0; i < 16; i++) {
                float w = ws[qg * 16 + i][kk];
                acc[i][0] = fmaf(w, v0, acc[i][0]);
                acc[i][1] = fmaf(w, v1, acc[i][1]);
                acc[i][2] = fmaf(w, v2, acc[i][2]);
                acc[i][3] = fmaf(w, v3, acc[i][3]);
            }
        }
        __syncthreads();
    }

    #pragma unroll
    for (int i = 0; i < 16; i++)
        #pragma unroll
        for (int j = 0; j < 4; j++)
            o[(size_t)(qg * 16 + i) * D_ + dj + 64 * j] = acc[i][j];
}

// ---------------------------------------------------------------------------
extern "C" void kernel_launch(void* const* d_in, const int* in_sizes, int n_in,
                              void* d_out, int out_size)
{
    const float* queries = (const float*)d_in[0];
    const float* keys    = (const float*)d_in[1];
    const float* values1 = (const float*)d_in[2];
    const void*  mask1   = d_in[3];
    const float* values2 = (const float*)d_in[4];
    const void*  mask2   = d_in[5];
    const float* Wq      = (const float*)d_in[6];
    const float* Wk      = (const float*)d_in[7];
    const float* scaling = (const float*)d_in[8];
    float* out = (float*)d_out;

    detect_mask_kernel<<<1, 256>>>((const unsigned char*)mask1);
    build_mask_kernel<<<(B_ * LK_ + 255) / 256, 256>>>(mask1, mask2);

    proj_kernel<<<dim3((B_ * LQ_) / 64, 2), 256>>>(queries, keys, Wq, Wk, scaling);

    scores_kernel<<<dim3(LK_ / 64, LQ_ / 64, B_), 256>>>();

    stats1_kernel<<<B_ * LQ_, 256>>>();
    stats2_kernel<<<dim3(LK_ / 64, B_), 256>>>();

    branch_kernel<<<dim3(32, B_, 2), 256>>>(values1, values2, out);
}